// round 15
// baseline (speedup 1.0000x reference)
#include <cuda_runtime.h>
#include <cstdint>

// Fused binarize + fixup using 256-bit global accesses (sm_100+ ld/st.global.v8.f32
// -> LDG.E.256 / STG.256). Same measured-best structure as R6/R11: 2 vectors per
// thread in coalesced-stride layout, predicate loads hoisted before bulk loads,
// default cache policy (both streaming-hint arms measured as regressions).
//
// All edit predicates depend only on the ORIGINAL Pid (the reference computes
// them pre-edit), and the 8 edited cells are pairwise distinct when valid, so
// each thread patches its own cells independently before storing.

#define LDG256(v, ptr)                                                        \
    asm volatile("ld.global.v8.f32 {%0,%1,%2,%3,%4,%5,%6,%7}, [%8];"          \
                 : "=f"((v)[0]), "=f"((v)[1]), "=f"((v)[2]), "=f"((v)[3]),    \
                   "=f"((v)[4]), "=f"((v)[5]), "=f"((v)[6]), "=f"((v)[7])     \
                 : "l"(ptr))

#define STG256(ptr, v)                                                        \
    asm volatile("st.global.v8.f32 [%0], {%1,%2,%3,%4,%5,%6,%7,%8};"          \
                 :: "l"(ptr),                                                 \
                    "f"((v)[0]), "f"((v)[1]), "f"((v)[2]), "f"((v)[3]),       \
                    "f"((v)[4]), "f"((v)[5]), "f"((v)[6]), "f"((v)[7])        \
                 : "memory")

__device__ __forceinline__ void apply_fix8(float* v, int inb, bool doFix,
                                           const int* rr, const int* cc,
                                           const float* vv) {
    if (!doFix) return;
    int r  = inb >> 6;          // row within batch (64 float8 per 512-col row)
    int c0 = (inb & 63) << 3;   // first column of this float8
    #pragma unroll
    for (int k = 0; k < 8; k++) {
        if (r == rr[k]) {
            int d = cc[k] - c0;
            if (d >= 0 && d < 8) v[d] = vv[k];
        }
    }
}

__global__ __launch_bounds__(256)
void binarize_fused_kernel(const float* __restrict__ pid,
                           const int* __restrict__ inter,
                           float* __restrict__ out,
                           long long half, int ncopies) {
    int bb = blockIdx.x;
    int batch = bb >> 6;                          // 64 blocks per batch
    int inb0 = ((bb & 63) << 9) | threadIdx.x;    // first float8 idx in batch
    int inb1 = inb0 + 256;                        // second (coalesced stride)
    long long base = (long long)batch << 18;      // batch * 512*512 floats
    const float* src0 = pid + base + ((long long)inb0 << 3);
    const float* src1 = pid + base + ((long long)inb1 << 3);
    float* dst0 = out + base + ((long long)inb0 << 3);
    float* dst1 = out + base + ((long long)inb1 << 3);

    // --- Small uniform loads first (latency covered by bulk loads below) ---
    int e10 = __ldg(inter + batch * 4 + 0);
    int e11 = __ldg(inter + batch * 4 + 1);
    int e20 = __ldg(inter + batch * 4 + 2);
    int e21 = __ldg(inter + batch * 4 + 3);

    // --- Bulk 256-bit loads (MLP=2 per thread) ---
    float p0[8], p1[8];
    LDG256(p0, src0);
    LDG256(p1, src1);

    bool distinct = (e10 != e11) && (e10 != e20) && (e10 != e21) &&
                    (e11 != e20) && (e11 != e21) && (e20 != e21);
    bool doFix = false;
    float oldp = 0.f;
    if (distinct) {
        bool blocked = (__ldg(pid + base + e10 * 512 + e20) > 0.f) ||
                       (__ldg(pid + base + e11 * 512 + e21) > 0.f);
        if (!blocked) {
            doFix = true;
            oldp = (__ldg(pid + base + e10 * 512 + e11) > 0.f) ? 1.f : 0.f;
        }
    }

    float v0[8], v1[8];
    #pragma unroll
    for (int k = 0; k < 8; k++) v0[k] = p0[k] > 0.f ? 1.f : 0.f;
    #pragma unroll
    for (int k = 0; k < 8; k++) v1[k] = p1[k] > 0.f ? 1.f : 0.f;

    int   rr[8] = {e10, e11, e20, e21, e10, e20, e11, e21};
    int   cc[8] = {e11, e10, e21, e20, e20, e10, e21, e11};
    float vv[8] = {0.f, 0.f, 0.f, 0.f, oldp, oldp, 1.f, 1.f};
    apply_fix8(v0, inb0, doFix, rr, cc, vv);
    apply_fix8(v1, inb1, doFix, rr, cc, vv);

    STG256(dst0, v0);
    STG256(dst1, v1);
    if (ncopies > 1) {
        STG256(dst0 + half, v0);
        STG256(dst1 + half, v1);
    }
}

extern "C" void kernel_launch(void* const* d_in, const int* in_sizes, int n_in,
                              void* d_out, int out_size) {
    const float* pid  = (const float*)d_in[0];   // (B, V, V) float32, V=512
    const int* inter  = (const int*)d_in[1];     // (B, 2, 2) int32
    float* out = (float*)d_out;

    const int V = 512;
    long long N = (long long)in_sizes[0];          // B*V*V
    int B = (int)(N / ((long long)V * V));         // 256
    int ncopies = (int)((long long)out_size / N);  // 2
    if (ncopies < 1) ncopies = 1;
    if (ncopies > 2) ncopies = 2;

    // 64 blocks per batch, 256 threads, 2 float8 per thread (64B/thread).
    unsigned blocks = (unsigned)B * 64u;
    binarize_fused_kernel<<<blocks, 256>>>(pid, inter, out, N, ncopies);
}

// round 16
// speedup vs baseline: 1.1519x; 1.1519x over previous
#include <cuda_runtime.h>
#include <cstdint>

// FINAL FORM — measured-best configuration (R6/R11), roofline-limited.
// Fused binarize + fixup: 2 float4 per thread in coalesced-stride layout
// (thread t handles batch-local float4 indices inb0 and inb0+512 here with
// 512-thread blocks; consecutive lanes hit consecutive addresses — full
// 128B-line coalescing per LDG.128/STG.128). Default cache policy: __ldcs,
// __stcs, and LDG.256 all measured as regressions on this chip. Per-batch
// predicate loads hoisted before the bulk loads so their latency is covered.
//
// All edit predicates depend only on the ORIGINAL Pid (the reference computes
// them pre-edit), and the 8 edited cells are pairwise distinct when valid, so
// each thread patches its own cells independently before storing.
__device__ __forceinline__ void apply_fix(float4& v, int inb, bool doFix,
                                          const int* rr, const int* cc,
                                          const float* vv) {
    if (!doFix) return;
    int r  = inb >> 7;          // row within batch (128 float4 per 512-col row)
    int c0 = (inb & 127) << 2;  // first column of this float4
    #pragma unroll
    for (int k = 0; k < 8; k++) {
        if (r == rr[k]) {
            int d = cc[k] - c0;
            if (d == 0) v.x = vv[k];
            else if (d == 1) v.y = vv[k];
            else if (d == 2) v.z = vv[k];
            else if (d == 3) v.w = vv[k];
        }
    }
}

__global__ __launch_bounds__(512)
void binarize_fused_kernel(const float4* __restrict__ pid4,
                           const float* __restrict__ pid,
                           const int* __restrict__ inter,
                           float4* __restrict__ out,
                           long long half4, int ncopies) {
    int bb = blockIdx.x;
    int batch = bb >> 6;                           // 64 blocks per batch
    int inb0 = ((bb & 63) << 10) | threadIdx.x;    // first float4 idx in batch
    int inb1 = inb0 + 512;                         // second (coalesced stride)
    long long base4 = (long long)batch << 16;      // batch * 65536 float4s
    long long i0 = base4 + inb0;
    long long i1 = base4 + inb1;

    // --- Small uniform loads first (latency covered by bulk loads below) ---
    int e10 = __ldg(inter + batch * 4 + 0);
    int e11 = __ldg(inter + batch * 4 + 1);
    int e20 = __ldg(inter + batch * 4 + 2);
    int e21 = __ldg(inter + batch * 4 + 3);

    // --- Bulk streaming loads (MLP=2 per thread) ---
    float4 p0 = pid4[i0];
    float4 p1 = pid4[i1];

    bool distinct = (e10 != e11) && (e10 != e20) && (e10 != e21) &&
                    (e11 != e20) && (e11 != e21) && (e20 != e21);
    bool doFix = false;
    float oldp = 0.f;
    if (distinct) {
        long long base = (long long)batch << 18;   // batch * 512*512
        bool blocked = (__ldg(pid + base + e10 * 512 + e20) > 0.f) ||
                       (__ldg(pid + base + e11 * 512 + e21) > 0.f);
        if (!blocked) {
            doFix = true;
            oldp = (__ldg(pid + base + e10 * 512 + e11) > 0.f) ? 1.f : 0.f;
        }
    }

    float4 v0, v1;
    v0.x = p0.x > 0.f ? 1.f : 0.f; v0.y = p0.y > 0.f ? 1.f : 0.f;
    v0.z = p0.z > 0.f ? 1.f : 0.f; v0.w = p0.w > 0.f ? 1.f : 0.f;
    v1.x = p1.x > 0.f ? 1.f : 0.f; v1.y = p1.y > 0.f ? 1.f : 0.f;
    v1.z = p1.z > 0.f ? 1.f : 0.f; v1.w = p1.w > 0.f ? 1.f : 0.f;

    int   rr[8] = {e10, e11, e20, e21, e10, e20, e11, e21};
    int   cc[8] = {e11, e10, e21, e20, e20, e10, e21, e11};
    float vv[8] = {0.f, 0.f, 0.f, 0.f, oldp, oldp, 1.f, 1.f};
    apply_fix(v0, inb0, doFix, rr, cc, vv);
    apply_fix(v1, inb1, doFix, rr, cc, vv);

    out[i0] = v0;
    out[i1] = v1;
    if (ncopies > 1) {
        out[i0 + half4] = v0;
        out[i1 + half4] = v1;
    }
}

extern "C" void kernel_launch(void* const* d_in, const int* in_sizes, int n_in,
                              void* d_out, int out_size) {
    const float* pid  = (const float*)d_in[0];   // (B, V, V) float32, V=512
    const int* inter  = (const int*)d_in[1];     // (B, 2, 2) int32
    float* out = (float*)d_out;

    const int V = 512;
    long long N = (long long)in_sizes[0];          // B*V*V
    int B = (int)(N / ((long long)V * V));         // 256
    int ncopies = (int)((long long)out_size / N);  // 2
    if (ncopies < 1) ncopies = 1;
    if (ncopies > 2) ncopies = 2;

    // 64 blocks per batch, 512 threads, 2 float4 per thread.
    unsigned blocks = (unsigned)B * 64u;
    binarize_fused_kernel<<<blocks, 512>>>(
        (const float4*)pid, pid, inter, (float4*)out, N / 4, ncopies);
}

// round 17
// speedup vs baseline: 1.1623x; 1.0090x over previous
#include <cuda_runtime.h>
#include <cstdint>

// FINAL — measured-best configuration across 15 rounds (120.74 us, DRAM-
// roofline-limited at ~6.45 TB/s on a compulsory 1-read:2-write 768 MB stream).
// Fused binarize + fixup: 2 float4 per thread in coalesced-stride layout
// (thread t handles batch-local float4 indices inb0 and inb0+256; consecutive
// lanes hit consecutive addresses — full 128B-line coalescing per
// LDG.128/STG.128). Default cache policy: __ldcs, __stcs, LDG.256, MLP=4,
// 512-thread blocks all measured as neutral-or-regressions on this chip.
//
// All edit predicates depend only on the ORIGINAL Pid (the reference computes
// them pre-edit), and the 8 edited cells are pairwise distinct when valid, so
// each thread patches its own cells independently before storing.
__device__ __forceinline__ void apply_fix(float4& v, int inb, bool doFix,
                                          const int* rr, const int* cc,
                                          const float* vv) {
    if (!doFix) return;
    int r  = inb >> 7;          // row within batch (128 float4 per 512-col row)
    int c0 = (inb & 127) << 2;  // first column of this float4
    #pragma unroll
    for (int k = 0; k < 8; k++) {
        if (r == rr[k]) {
            int d = cc[k] - c0;
            if (d == 0) v.x = vv[k];
            else if (d == 1) v.y = vv[k];
            else if (d == 2) v.z = vv[k];
            else if (d == 3) v.w = vv[k];
        }
    }
}

__global__ __launch_bounds__(256)
void binarize_fused_kernel(const float4* __restrict__ pid4,
                           const float* __restrict__ pid,
                           const int* __restrict__ inter,
                           float4* __restrict__ out,
                           long long half4, int ncopies) {
    int bb = blockIdx.x;
    int batch = bb >> 7;                           // 128 blocks per batch
    int inb0 = ((bb & 127) << 9) | threadIdx.x;    // first float4 idx in batch
    int inb1 = inb0 + 256;                         // second (coalesced stride)
    long long base4 = (long long)batch << 16;      // batch * 65536 float4s
    long long i0 = base4 + inb0;
    long long i1 = base4 + inb1;

    // Bulk streaming loads batched up front (MLP=2 per thread).
    float4 p0 = pid4[i0];
    float4 p1 = pid4[i1];

    float4 v0, v1;
    v0.x = p0.x > 0.f ? 1.f : 0.f; v0.y = p0.y > 0.f ? 1.f : 0.f;
    v0.z = p0.z > 0.f ? 1.f : 0.f; v0.w = p0.w > 0.f ? 1.f : 0.f;
    v1.x = p1.x > 0.f ? 1.f : 0.f; v1.y = p1.y > 0.f ? 1.f : 0.f;
    v1.z = p1.z > 0.f ? 1.f : 0.f; v1.w = p1.w > 0.f ? 1.f : 0.f;

    // Per-batch edit decision (uniform per block; same-address loads broadcast).
    int e10 = __ldg(inter + batch * 4 + 0);
    int e11 = __ldg(inter + batch * 4 + 1);
    int e20 = __ldg(inter + batch * 4 + 2);
    int e21 = __ldg(inter + batch * 4 + 3);

    bool distinct = (e10 != e11) && (e10 != e20) && (e10 != e21) &&
                    (e11 != e20) && (e11 != e21) && (e20 != e21);
    bool doFix = false;
    float oldp = 0.f;
    if (distinct) {
        long long base = (long long)batch << 18;   // batch * 512*512
        bool blocked = (__ldg(pid + base + e10 * 512 + e20) > 0.f) ||
                       (__ldg(pid + base + e11 * 512 + e21) > 0.f);
        if (!blocked) {
            doFix = true;
            oldp = (__ldg(pid + base + e10 * 512 + e11) > 0.f) ? 1.f : 0.f;
        }
    }

    int   rr[8] = {e10, e11, e20, e21, e10, e20, e11, e21};
    int   cc[8] = {e11, e10, e21, e20, e20, e10, e21, e11};
    float vv[8] = {0.f, 0.f, 0.f, 0.f, oldp, oldp, 1.f, 1.f};
    apply_fix(v0, inb0, doFix, rr, cc, vv);
    apply_fix(v1, inb1, doFix, rr, cc, vv);

    out[i0] = v0;
    out[i1] = v1;
    if (ncopies > 1) {
        out[i0 + half4] = v0;
        out[i1 + half4] = v1;
    }
}

extern "C" void kernel_launch(void* const* d_in, const int* in_sizes, int n_in,
                              void* d_out, int out_size) {
    const float* pid  = (const float*)d_in[0];   // (B, V, V) float32, V=512
    const int* inter  = (const int*)d_in[1];     // (B, 2, 2) int32
    float* out = (float*)d_out;

    const int V = 512;
    long long N = (long long)in_sizes[0];          // B*V*V
    int B = (int)(N / ((long long)V * V));         // 256
    int ncopies = (int)((long long)out_size / N);  // 2
    if (ncopies < 1) ncopies = 1;
    if (ncopies > 2) ncopies = 2;

    // 128 blocks per batch, 256 threads, 2 float4 per thread.
    unsigned blocks = (unsigned)B * 128u;
    binarize_fused_kernel<<<blocks, 256>>>(
        (const float4*)pid, pid, inter, (float4*)out, N / 4, ncopies);
}